// round 17
// baseline (speedup 1.0000x reference)
#include <cuda_runtime.h>
#include <cuda_fp16.h>
#include <math.h>
#include <stdint.h>

// Problem constants
#define BB 256
#define PP 5
#define TT 256
#define FF 128
#define HH 512
#define CC 60
#define DD 640      // P*F
#define G4 2048     // 4*H
#define MM 65536    // T*B rows

// Scratch (device globals: allocation-free per harness rules)
__device__ float g_xw[134217728ULL];           // (T*B) x [ch*4+gate] fp32
__device__ __half g_xh[(size_t)MM * DD];       // x fp16, [m][k]
__device__ __half g_wh[(size_t)G4 * DD];       // Wx fp16, [n'][k], n'=ch*4+gate
__device__ float g_bp[G4];                     // permuted bias
__device__ float g_h[BB * HH];                 // final h fp32 (for head)
__device__ __half g_hh[2][BB][HH];             // [buf][row][ch] fp16 h
__device__ float g_kg[TT * HH];                // time gate k(t,ch)
__device__ unsigned g_flag[8][16];             // per (m-group, producer) step flags

// ---------------------------------------------------------------------------
// Fast gate nonlinearities (error ~2^-22, invisible at 5e-6 rel_err)
// ---------------------------------------------------------------------------
__device__ __forceinline__ float sigmoid_f(float x) {
    return __fdividef(1.0f, 1.0f + __expf(-x));
}
__device__ __forceinline__ float tanh_f(float x) {
    return 1.0f - __fdividef(2.0f, __expf(2.0f * x) + 1.0f);
}

// ---------------------------------------------------------------------------
// MMA helpers (HMMA SASS; fragment patterns proven in R12-R16)
// ---------------------------------------------------------------------------
__device__ __forceinline__ void ldsm4(unsigned* r, uint32_t addr) {
    asm volatile("ldmatrix.sync.aligned.m8n8.x4.shared.b16 {%0, %1, %2, %3}, [%4];"
                 : "=r"(r[0]), "=r"(r[1]), "=r"(r[2]), "=r"(r[3]) : "r"(addr));
}

__device__ __forceinline__ void mma_fp16(float* d, const unsigned* a, const unsigned* b) {
    asm volatile(
        "mma.sync.aligned.m16n8k16.row.col.f32.f16.f16.f32 "
        "{%0, %1, %2, %3}, {%4, %5, %6, %7}, {%8, %9}, {%0, %1, %2, %3};"
        : "+f"(d[0]), "+f"(d[1]), "+f"(d[2]), "+f"(d[3])
        : "r"(a[0]), "r"(a[1]), "r"(a[2]), "r"(a[3]), "r"(b[0]), "r"(b[1]));
}

// ---------------------------------------------------------------------------
// Init / prep kernels
// ---------------------------------------------------------------------------
__global__ void zero_state() {
    int i = blockIdx.x * blockDim.x + threadIdx.x;
    if (i < 65536) ((float*)g_hh)[i] = 0.0f;   // zero g_hh[0] (256*512 fp16)
    if (i < 128) ((unsigned*)g_flag)[i] = 0u;
}

__global__ void kg_kernel(const float* __restrict__ tau,
                          const float* __restrict__ shift) {
    int i = blockIdx.x * blockDim.x + threadIdx.x;
    if (i < TT * HH) {
        int t = i >> 9, ch = i & 511;
        float tv = tau[ch], sv = shift[ch];
        float xph = ((float)t - sv) / tv;
        float phi = xph - floorf(xph);
        float kg = (phi < 0.025f) ? (40.0f * phi)
                 : (phi < 0.05f)  ? (2.0f - 40.0f * phi)
                                  : (0.001f * phi);
        g_kg[i] = kg;
    }
}

// X (B,P,T,F) fp32 -> g_xh [m][k] fp16, m = t*256+b, k = p*128+f
__global__ void xprep(const float* __restrict__ X) {
    size_t idx = (size_t)blockIdx.x * blockDim.x + threadIdx.x;
    if (idx >= (size_t)MM * 160) return;
    int m  = (int)(idx / 160);
    int kq = (int)(idx % 160) * 4;
    int t = m >> 8, b = m & 255;
    int p = kq >> 7, f = kq & 127;
    float4 v = *(const float4*)&X[(((size_t)b * PP + p) * TT + t) * FF + f];
    __half h4[4] = {__float2half(v.x), __float2half(v.y),
                    __float2half(v.z), __float2half(v.w)};
    *(uint2*)&g_xh[(size_t)m * DD + kq] = *(uint2*)h4;
}

// Wx [k][4H] fp32 -> g_wh [n'][k] fp16, n' = ch*4 + gate (wcol = gate*512+ch)
__global__ void wprep(const float* __restrict__ Wx, const float* __restrict__ bvec) {
    int idx = blockIdx.x * blockDim.x + threadIdx.x;
    if (idx >= G4 * 160) return;
    int np = idx / 160;
    int kq = (idx % 160) * 4;
    int gate = np & 3, ch = np >> 2;
    int wcol = gate * HH + ch;
    __half h4[4];
#pragma unroll
    for (int j = 0; j < 4; ++j)
        h4[j] = __float2half(Wx[(size_t)(kq + j) * G4 + wcol]);
    *(uint2*)&g_wh[(size_t)np * DD + kq] = *(uint2*)h4;
    if (kq == 0) g_bp[np] = bvec[wcol];
}

// ---------------------------------------------------------------------------
// Phase 1: XW GEMM on mma.sync, single fp16 product (unchanged from R15/16).
// ---------------------------------------------------------------------------
#define XSM_A 0          // A: [buf][128 rows][48B]
#define XSM_B 12288      // B: [buf][128 rows][48B]
#define XSM_TOT 24576

__global__ void __launch_bounds__(256, 2)
xw_mma(int dummy) {
    extern __shared__ char smc[];
    const uint32_t sb = (uint32_t)__cvta_generic_to_shared(smc);
    const int tid  = threadIdx.x;
    const int wid  = tid >> 5;
    const int lane = tid & 31;
    const int n0   = blockIdx.x << 7;
    const int m0   = blockIdx.y << 7;
    const int mw   = wid & 3;
    const int nw   = wid >> 2;

    const int a_row = mw * 32 + (lane & 7) + ((lane >> 3) & 1) * 8;
    const uint32_t aOff = sb + XSM_A + a_row * 48 + ((lane >> 4) & 1) * 16;
    const int b_row = (lane & 7) + ((lane >> 4) & 1) * 8;
    const uint32_t bOff = sb + XSM_B + (nw * 64 + b_row) * 48 + ((lane >> 3) & 1) * 16;

    const int arow = tid >> 1;
    const int ahf  = tid & 1;

    float d[2][8][4];
#pragma unroll
    for (int i = 0; i < 2; ++i)
#pragma unroll
        for (int j = 0; j < 8; ++j)
#pragma unroll
            for (int q = 0; q < 4; ++q) d[i][j][q] = 0.f;

    uint4 pa, pb;
    auto ldg = [&](int k0) {
        pa = *(const uint4*)&g_xh[(size_t)(m0 + arow) * DD + k0 + ahf * 8];
        pb = *(const uint4*)&g_wh[(size_t)(n0 + arow) * DD + k0 + ahf * 8];
    };
    auto sts = [&](int buf) {
        *(uint4*)(smc + XSM_A + buf * 6144 + arow * 48 + ahf * 16) = pa;
        *(uint4*)(smc + XSM_B + buf * 6144 + arow * 48 + ahf * 16) = pb;
    };

    ldg(0);
    sts(0);
    __syncthreads();

    for (int s = 0; s < 40; ++s) {
        const int buf = s & 1;
        if (s < 39) ldg((s + 1) * 16);

        unsigned bq[4][4];
#pragma unroll
        for (int p4 = 0; p4 < 4; ++p4)
            ldsm4(bq[p4], bOff + buf * 6144 + p4 * 16 * 48);
#pragma unroll
        for (int mt = 0; mt < 2; ++mt) {
            unsigned ah[4];
            ldsm4(ah, aOff + buf * 6144 + mt * 16 * 48);
#pragma unroll
            for (int p4 = 0; p4 < 4; ++p4) {
                mma_fp16(d[mt][2 * p4],     ah, bq[p4] + 0);
                mma_fp16(d[mt][2 * p4 + 1], ah, bq[p4] + 2);
            }
        }
        if (s < 39) sts(buf ^ 1);
        __syncthreads();
    }

    const int gr = lane >> 2;
    const int tc = lane & 3;
#pragma unroll
    for (int mt = 0; mt < 2; ++mt) {
        const int r0 = m0 + mw * 32 + mt * 16 + gr;
#pragma unroll
        for (int n8 = 0; n8 < 8; ++n8) {
            const int col = n0 + nw * 64 + n8 * 8 + tc * 2;
            float2 bs = *(const float2*)&g_bp[col];
            *(float2*)&g_xw[(size_t)r0 * G4 + col] =
                make_float2(d[mt][n8][0] + bs.x, d[mt][n8][1] + bs.y);
            *(float2*)&g_xw[(size_t)(r0 + 8) * G4 + col] =
                make_float2(d[mt][n8][2] + bs.x, d[mt][n8][3] + bs.y);
        }
    }
}

// ---------------------------------------------------------------------------
// Phase 2: PERSISTENT recurrence (R16 tiling) + producer-flag exchange.
//   Grid (16, 8) = 128 blocks, 256 threads (8 warps).
//   Block: M=32 rows x N=128 cols (32 ch x 4 gates, n = chl*4+gate), K=512.
//   Warp (mt = wid&1 -> m16, nq = wid>>1 -> n32 = 8 channels).
//   Exchange: per-producer flags; each staging thread waits only on the 2
//   blocks producing its 64-ch span, then LDG+STS immediately. Union of all
//   ksegs + block syncthreads preserves the full-group transitive barrier.
// ---------------------------------------------------------------------------
#define RPITCH 1040                      // bytes per smem row (512 fp16 + pad)
#define SM_B   0                         // 128 rows
#define SM_A   133120                    // 32 rows
#define SMEM_TOTAL 166400

__global__ void __launch_bounds__(256, 1)
plstm_mma(const float* __restrict__ Wh) {
    extern __shared__ char smc[];
    const uint32_t sb = (uint32_t)__cvta_generic_to_shared(smc);
    const int tid  = threadIdx.x;
    const int wid  = tid >> 5;
    const int lane = tid & 31;
    const int ch0  = blockIdx.x << 5;     // 16 ch-tiles of 32 channels
    const int mg   = blockIdx.y;          // 0..7 row group (32 rows)
    const int m0   = mg << 5;
    const int mt   = wid & 1;             // m16 tile
    const int nq   = wid >> 1;            // n32 slice (8 channels)

    // ---- prologue: Wh -> smem BT[n][k] fp16, n = chl*4 + gate ----
    {
        const int chl = tid & 31;
        const int gt  = (tid >> 5) & 3;
        const int kh  = tid >> 7;                 // 0/1
        const float* wp = &Wh[(size_t)(kh * 256) * G4 + gt * HH + ch0 + chl];
        char* bh = smc + SM_B + (chl * 4 + gt) * RPITCH + kh * 512;
        for (int k = 0; k < 256; ++k)
            *(__half*)(bh + k * 2) = __float2half(wp[(size_t)k * G4]);
    }

    // ldsm addresses
    const int a_row = mt * 16 + (lane & 7) + ((lane >> 3) & 1) * 8;
    const uint32_t aH = sb + SM_A + a_row * RPITCH + ((lane >> 4) & 1) * 16;
    const int b_row = (lane & 7) + ((lane >> 4) & 1) * 8;
    const uint32_t bH = sb + SM_B + (nq * 32 + b_row) * RPITCH + ((lane >> 3) & 1) * 16;

    // A staging: thread -> (row sr, k-seg of 64 fp16); producers kseg*2, +1
    const int sr   = tid >> 3;            // 0..31
    const int kseg = tid & 7;             // 0..7
    volatile unsigned* f0 = &g_flag[mg][kseg * 2];
    volatile unsigned* f1 = &g_flag[mg][kseg * 2 + 1];

    // epilogue mapping
    const int gr = lane >> 2;
    const int tc = lane & 3;
    const int row = m0 + mt * 16 + gr + (tc & 1) * 8;

    float cs[4], hs[4];
#pragma unroll
    for (int j = 0; j < 4; ++j) { cs[j] = 0.f; hs[j] = 0.f; }

    __syncthreads();   // B ready

    for (int t = 0; t < TT; ++t) {
        const int hb = t & 1;

        // prefetch xw + kg first (independent of h -> overlaps flag wait)
        float4 xw_r[4];
        float  kg_r[4];
#pragma unroll
        for (int dq = 0; dq < 4; ++dq) {
            const int ch = ch0 + nq * 8 + dq * 2 + (tc >> 1);
            xw_r[dq] = *(const float4*)&g_xw[((size_t)t * BB + row) * G4 + ch * 4];
            kg_r[dq] = g_kg[t * HH + ch];
        }

        // ---- wait only this thread's 2 producers, then stage its piece ----
        if (t > 0) {
            const unsigned tgt = (unsigned)t;
            unsigned v;
            do {
                asm volatile("ld.acquire.gpu.global.u32 %0, [%1];"
                             : "=r"(v) : "l"((const unsigned*)f0) : "memory");
            } while (v < tgt);
            do {
                asm volatile("ld.acquire.gpu.global.u32 %0, [%1];"
                             : "=r"(v) : "l"((const unsigned*)f1) : "memory");
            } while (v < tgt);
        }
        {
            const __half* hp = &g_hh[hb][m0 + sr][kseg * 64];
            uint4 v[8];
#pragma unroll
            for (int j = 0; j < 8; ++j) v[j] = ((const uint4*)hp)[j];
            char* dst = smc + SM_A + sr * RPITCH + kseg * 128;
#pragma unroll
            for (int j = 0; j < 8; ++j) *(uint4*)(dst + j * 16) = v[j];
        }
        __syncthreads();

        // ---- MMA: m16n32k512 per warp = 32 ksteps x 4 MMAs ----
        float d[4][4];
#pragma unroll
        for (int j = 0; j < 4; ++j)
#pragma unroll
            for (int q = 0; q < 4; ++q) d[j][q] = 0.f;

#pragma unroll
        for (int ks = 0; ks < 32; ++ks) {
            unsigned ah4[4];
            ldsm4(ah4, aH + ks * 32);
#pragma unroll
            for (int np2 = 0; np2 < 2; ++np2) {
                unsigned bh4[4];
                ldsm4(bh4, bH + (uint32_t)(np2 * 16 * RPITCH + ks * 32));
                mma_fp16(d[np2 * 2],     ah4, bh4 + 0);
                mma_fp16(d[np2 * 2 + 1], ah4, bh4 + 2);
            }
        }

        // ---- fused epilogue: gate regroup (shfl), fast gates, update ----
        const int nb = (t + 1) & 1;
#pragma unroll
        for (int dq = 0; dq < 4; ++dq) {
            float s0 = __shfl_xor_sync(0xffffffffu, (tc & 1) ? d[dq][0] : d[dq][2], 1);
            float s1 = __shfl_xor_sync(0xffffffffu, (tc & 1) ? d[dq][1] : d[dq][3], 1);
            float gi, gf, gg, go;
            if (tc & 1) { gi = s0;       gf = s1;       gg = d[dq][2]; go = d[dq][3]; }
            else        { gi = d[dq][0]; gf = d[dq][1]; gg = s0;       go = s1; }
            const int ch = ch0 + nq * 8 + dq * 2 + (tc >> 1);
            float4 xw = xw_r[dq];
            float kg = kg_r[dq];
            gi = sigmoid_f(gi + xw.x);
            gf = sigmoid_f(gf + xw.y);
            gg = tanh_f(gg + xw.z);
            go = sigmoid_f(go + xw.w);
            float ct = gf * cs[dq] + gi * gg;
            float ht = go * tanh_f(ct);
            cs[dq] = kg * ct + (1.0f - kg) * cs[dq];
            float hn = kg * ht + (1.0f - kg) * hs[dq];
            hs[dq] = hn;
            g_hh[nb][row][ch] = __float2half(hn);
            if (t == TT - 1) g_h[(size_t)row * HH + ch] = hn;
        }

        // ---- publish: all block stores done -> flag = t+1 ----
        if (t < TT - 1) {
            __syncthreads();             // all epilogue stores issued (also guards SM_A reuse)
            if (tid == 0) {
                __threadfence();
                asm volatile("st.release.gpu.global.u32 [%0], %1;"
                             :: "l"(&g_flag[mg][blockIdx.x]), "r"((unsigned)(t + 1))
                             : "memory");
            }
        }
    }
}

// ---------------------------------------------------------------------------
// Phase 3: head (logits + log_softmax)
// ---------------------------------------------------------------------------
__global__ void head_kernel(const float* __restrict__ fc_w,
                            const float* __restrict__ fc_b,
                            float* __restrict__ out) {
    __shared__ float hrow[HH];
    __shared__ float part[CC][4];
    __shared__ float logits[CC];
    __shared__ float s_lse;
    const int b = blockIdx.x;
    const int tid = threadIdx.x;   // 256

    *(float2*)&hrow[tid * 2] = *(const float2*)&g_h[(size_t)b * HH + tid * 2];
    __syncthreads();

    const int c = tid >> 2;
    const int s = tid & 3;
    if (c < CC) {
        float sum = 0.0f;
        const float* wp = &fc_w[(size_t)(s * 128) * CC + c];
        const float* hp = &hrow[s * 128];
#pragma unroll 16
        for (int k = 0; k < 128; ++k) sum += hp[k] * wp[k * CC];
        part[c][s] = sum;
    }
    __syncthreads();

    if (tid < CC)
        logits[tid] = part[tid][0] + part[tid][1] + part[tid][2] + part[tid][3] + fc_b[tid];
    __syncthreads();

    if (tid == 0) {
        float mx = -1e30f;
        for (int i = 0; i < CC; ++i) mx = fmaxf(mx, logits[i]);
        float sm = 0.0f;
        for (int i = 0; i < CC; ++i) sm += expf(logits[i] - mx);
        s_lse = mx + logf(sm);
    }
    __syncthreads();

    if (tid < CC) out[(size_t)b * CC + tid] = logits[tid] - s_lse;
}

// ---------------------------------------------------------------------------
// Launch
// ---------------------------------------------------------------------------
extern "C" void kernel_launch(void* const* d_in, const int* in_sizes, int n_in,
                              void* d_out, int out_size) {
    const float* x     = (const float*)d_in[0];
    const float* Wx    = (const float*)d_in[1];
    const float* Wh    = (const float*)d_in[2];
    const float* bias  = (const float*)d_in[3];
    const float* tau   = (const float*)d_in[4];
    const float* shift = (const float*)d_in[5];
    const float* fc_w  = (const float*)d_in[6];
    const float* fc_b  = (const float*)d_in[7];
    float* out = (float*)d_out;

    cudaFuncSetAttribute(xw_mma,
                         cudaFuncAttributeMaxDynamicSharedMemorySize, XSM_TOT);
    cudaFuncSetAttribute(plstm_mma,
                         cudaFuncAttributeMaxDynamicSharedMemorySize, SMEM_TOTAL);

    zero_state<<<512, 256>>>();
    kg_kernel<<<512, 256>>>(tau, shift);
    xprep<<<(int)(((size_t)MM * 160 + 255) / 256), 256>>>(x);
    wprep<<<(G4 * 160 + 255) / 256, 256>>>(Wx, bias);

    dim3 g1(G4 / 128, MM / 128);          // (16, 512)
    xw_mma<<<g1, 256, XSM_TOT>>>(0);

    dim3 g2(16, 8);                        // 128 persistent blocks
    plstm_mma<<<g2, 256, SMEM_TOTAL>>>(Wh);

    head_kernel<<<BB, 256>>>(fc_w, fc_b, out);
}